// round 14
// baseline (speedup 1.0000x reference)
#include <cuda_runtime.h>
#include <cuda_fp16.h>
#include <math.h>
#include <cstdint>

#define MROWS 49152
#define CDIM  512
#define LDIM  24
#define HEADS 8
#define DHEAD 64

// ---------------------------------------------------------------------------
// Device scratch
// ---------------------------------------------------------------------------
__device__ float  g_tvi[LDIM * CDIM];
__device__ float  g_bvg[CDIM];
__device__ float  g_wvgp[8 * 512 * 512];
__device__ __half g_qi [MROWS * CDIM];
__device__ __half g_kvi[MROWS * CDIM];
__device__ __half g_qn [MROWS * CDIM];
__device__ __half g_kn [MROWS * CDIM];
__device__ __half g_vn [MROWS * CDIM];
__device__ __half g_xh [MROWS * CDIM];
// Transposed fp16 weights [N][K]: q:0, k:262144, vg:524288, m:786432
__device__ __half g_wt [1048576];

// ---------------------------------------------------------------------------
// PTX helpers
// ---------------------------------------------------------------------------
__device__ __forceinline__ uint32_t smem_u32(const void* p) {
    uint32_t a;
    asm("{ .reg .u64 t; cvta.to.shared.u64 t, %1; cvt.u32.u64 %0, t; }" : "=r"(a) : "l"(p));
    return a;
}
__device__ __forceinline__ void cp16(uint32_t s, const void* g) {
    asm volatile("cp.async.cg.shared.global [%0], [%1], 16;" :: "r"(s), "l"(g));
}
#define CP_COMMIT() asm volatile("cp.async.commit_group;")
#define CP_WAIT(n)  asm volatile("cp.async.wait_group %0;" :: "n"(n))

#define LDSM4(r, a)                                                        \
    asm volatile("ldmatrix.sync.aligned.m8n8.x4.shared.b16 {%0,%1,%2,%3}, [%4];" \
        : "=r"((r)[0]), "=r"((r)[1]), "=r"((r)[2]), "=r"((r)[3]) : "r"(a))

#define LDSM4T(r, a)                                                       \
    asm volatile("ldmatrix.sync.aligned.m8n8.x4.trans.shared.b16 {%0,%1,%2,%3}, [%4];" \
        : "=r"((r)[0]), "=r"((r)[1]), "=r"((r)[2]), "=r"((r)[3]) : "r"(a))

#define MMA16816(c, a, b0, b1)                                             \
    asm volatile(                                                          \
        "mma.sync.aligned.m16n8k16.row.col.f32.f16.f16.f32 "               \
        "{%0,%1,%2,%3},{%4,%5,%6,%7},{%8,%9},{%0,%1,%2,%3};"               \
        : "+f"((c)[0]), "+f"((c)[1]), "+f"((c)[2]), "+f"((c)[3])           \
        : "r"((a)[0]), "r"((a)[1]), "r"((a)[2]), "r"((a)[3]),              \
          "r"(b0), "r"(b1))

// ---------------------------------------------------------------------------
// 1) conv_both (R9-exact)
// ---------------------------------------------------------------------------
#define N4 (MROWS * CDIM / 4)
__global__ void conv_both(const float* __restrict__ q, const float* __restrict__ kv,
                          __half* __restrict__ qi, __half* __restrict__ kvi) {
    int i = blockIdx.x * 256 + threadIdx.x;
    const float* src = (i < N4) ? q : kv;
    __half* dst = (i < N4) ? qi : kvi;
    int j = (i < N4) ? i : i - N4;
    float4 v = reinterpret_cast<const float4*>(src)[j];
    reinterpret_cast<__half2*>(dst)[j * 2 + 0] = __floats2half2_rn(v.x, v.y);
    reinterpret_cast<__half2*>(dst)[j * 2 + 1] = __floats2half2_rn(v.z, v.w);
}

// ---------------------------------------------------------------------------
// 2) prepare (R9-exact: transposes + compose partials + tanh + fold)
// ---------------------------------------------------------------------------
__global__ void __launch_bounds__(256)
prepare(const float* __restrict__ Wq, const float* __restrict__ Wkv,
        const float* __restrict__ Wg, const float* __restrict__ Wm,
        const float* __restrict__ bkv, const float* __restrict__ bg,
        const float* __restrict__ v_init,
        __half* __restrict__ wt, float* __restrict__ wvgp,
        float* __restrict__ tvi, float* __restrict__ bvg)
{
    __shared__ float t[32][33];
    __shared__ float As[16][128];
    __shared__ float Bs[16][128];

    const int bx = blockIdx.x;
    const int tx = threadIdx.x & 31;
    const int ty = threadIdx.x >> 5;
    const int flat = threadIdx.x;

    if (bx < 768) {
        const int seg = bx >> 8;
        const int local = bx & 255;
        const int n0 = (local & 15) * 32, k0 = (local >> 4) * 32;
        const float* W = (seg == 0) ? Wq : (seg == 1) ? Wkv : Wm;
        const int N = (seg == 1) ? 1024 : 512;
        __half* dst = wt + ((seg == 0) ? 0 : (seg == 1) ? 262144 : 786432);
        #pragma unroll
        for (int i = 0; i < 32; i += 8)
            t[ty + i][tx] = W[(size_t)(k0 + ty + i) * N + n0 + tx];
        __syncthreads();
        #pragma unroll
        for (int i = 0; i < 32; i += 8)
            dst[(size_t)(n0 + ty + i) * 512 + k0 + tx] = __float2half(t[tx][ty + i]);
    } else if (bx < 896) {
        const int local = bx - 768;
        const int tile = local >> 3, slice = local & 7;
        const int m0 = (tile >> 2) * 128, n0 = (tile & 3) * 128;
        const int j0 = slice * 64;
        const int px = flat & 15, py = flat >> 4;
        float acc[8][8];
        #pragma unroll
        for (int i = 0; i < 8; i++)
            #pragma unroll
            for (int j = 0; j < 8; j++) acc[i][j] = 0.0f;
        for (int jc = 0; jc < 64; jc += 16) {
            #pragma unroll
            for (int i = 0; i < 2; i++) {
                int lin = flat + i * 256;
                int ar = lin >> 2, ac = (lin & 3) * 4;
                float4 av = *reinterpret_cast<const float4*>(
                    Wkv + (size_t)(m0 + ar) * 1024 + 512 + j0 + jc + ac);
                As[ac + 0][ar] = av.x; As[ac + 1][ar] = av.y;
                As[ac + 2][ar] = av.z; As[ac + 3][ar] = av.w;
                int br = lin >> 5, bc = (lin & 31) * 4;
                *reinterpret_cast<float4*>(&Bs[br][bc]) =
                    *reinterpret_cast<const float4*>(Wg + (size_t)(j0 + jc + br) * 512 + n0 + bc);
            }
            __syncthreads();
            #pragma unroll
            for (int kk = 0; kk < 16; kk++) {
                float a[8], b[8];
                #pragma unroll
                for (int i = 0; i < 8; i++) { a[i] = As[kk][py * 8 + i]; b[i] = Bs[kk][px * 8 + i]; }
                #pragma unroll
                for (int i = 0; i < 8; i++)
                    #pragma unroll
                    for (int j = 0; j < 8; j++) acc[i][j] += a[i] * b[j];
            }
            __syncthreads();
        }
        #pragma unroll
        for (int i = 0; i < 8; i++)
            #pragma unroll
            for (int j = 0; j < 8; j++)
                wvgp[(size_t)slice * 262144 + (size_t)(m0 + py * 8 + i) * 512 + n0 + px * 8 + j] = acc[i][j];
    } else if (bx < 944) {
        int i = (bx - 896) * 256 + flat;
        tvi[i] = tanhf(v_init[i]);
    } else {
        int n = (bx - 944) * 256 + flat;
        if (n < 512) {
            float s = bg[n];
            for (int j = 0; j < 512; j++) s += bkv[512 + j] * Wg[(size_t)j * 512 + n];
            bvg[n] = s;
        }
    }
}

// ---------------------------------------------------------------------------
// 3) finish_wvg (R9-exact)
// ---------------------------------------------------------------------------
__global__ void __launch_bounds__(256)
finish_wvg(const float* __restrict__ wvgp, __half* __restrict__ wt) {
    __shared__ float t[32][33];
    const int nb = blockIdx.x & 15, mb = blockIdx.x >> 4;
    const int n0 = nb * 32, m0 = mb * 32;
    const int tx = threadIdx.x & 31, ty = threadIdx.x >> 5;
    #pragma unroll
    for (int i = 0; i < 32; i += 8) {
        float s = 0.0f;
        #pragma unroll
        for (int sl = 0; sl < 8; sl++)
            s += wvgp[(size_t)sl * 262144 + (size_t)(m0 + ty + i) * 512 + n0 + tx];
        t[ty + i][tx] = s;
    }
    __syncthreads();
    #pragma unroll
    for (int i = 0; i < 32; i += 8)
        wt[524288 + (size_t)(n0 + ty + i) * 512 + m0 + tx] = __float2half(t[tx][ty + i]);
}

// ---------------------------------------------------------------------------
// GEMM mainloop: CTA 128x128, FOUR warps of 64x64 (2m x 2n), 128 threads,
// BK=64, 2-stage, one barrier per chunk (wait -> sync -> load -> compute).
// 2 CTAs/SM preserved (smem 73728B, regs ~200 < 256 cap).
// Fragment bytes per MMA: 128B (vs 192B at 32x64) -> crossbar relief.
// ---------------------------------------------------------------------------
#define SROW 144
#define MAT  18432
#define BUF  36864

#define LOAD_CHUNK(c, buf) do {                                              \
    const int kc0 = (c) * 64;                                                \
    const uint32_t sb = smb + (buf) * BUF;                                   \
    _Pragma("unroll")                                                        \
    for (int it = 0; it < 8; it++) {                                         \
        const int row = lrow + it * 16;                                      \
        const uint32_t so = row * SROW + lkq * 16;                           \
        cp16(sb + so,       A + (size_t)(bm + row) * 512 + kc0 + lkq * 8);   \
        cp16(sb + MAT + so, B + (size_t)(bn + row) * 512 + kc0 + lkq * 8);   \
    }                                                                        \
    CP_COMMIT();                                                             \
} while (0)

#define GEMM_MAINLOOP()                                                      \
    LOAD_CHUNK(0, 0);                                                        \
    for (int c = 0; c < 8; c++) {                                            \
        const int buf = c & 1;                                               \
        CP_WAIT(0);                                                          \
        __syncthreads();                                                     \
        if (c < 7) LOAD_CHUNK(c + 1, buf ^ 1);                               \
        const uint32_t sb = smb + buf * BUF;                                 \
        _Pragma("unroll")                                                    \
        for (int ks = 0; ks < 4; ks++) {                                     \
            uint32_t afr[4][4], bfr[4][4];                                   \
            _Pragma("unroll")                                                \
            for (int mt = 0; mt < 4; mt++) {                                 \
                const int mrow = wm + mt * 16 + (lj & 1) * 8 + lr;           \
                const int kcol = ks * 16 + (lj >> 1) * 8;                    \
                LDSM4(afr[mt], sb + mrow * SROW + kcol * 2);                 \
            }                                                                \
            _Pragma("unroll")                                                \
            for (int np = 0; np < 4; np++) {                                 \
                const int nrow = wn + np * 16 + (lj >> 1) * 8 + lr;          \
                const int kcol = ks * 16 + (lj & 1) * 8;                     \
                LDSM4(bfr[np], sb + MAT + nrow * SROW + kcol * 2);           \
            }                                                                \
            _Pragma("unroll")                                                \
            for (int mt = 0; mt < 4; mt++)                                   \
                _Pragma("unroll")                                            \
                for (int nt = 0; nt < 8; nt++)                               \
                    MMA16816(acc[mt][nt], afr[mt],                           \
                             bfr[nt >> 1][(nt & 1) * 2],                     \
                             bfr[nt >> 1][(nt & 1) * 2 + 1]);                \
        }                                                                    \
    }

// ---------------------------------------------------------------------------
// 4) proj_mma: grid (12, 384), block 128
// ---------------------------------------------------------------------------
__global__ void __launch_bounds__(128, 2)
proj_mma(const __half* __restrict__ qi, const __half* __restrict__ kvi,
         const __half* __restrict__ wt,
         const float* __restrict__ bq, const float* __restrict__ bkv,
         const float* __restrict__ bvg, const float* __restrict__ tvi,
         __half* __restrict__ qn, __half* __restrict__ kn, __half* __restrict__ vn)
{
    extern __shared__ char sm[];
    const uint32_t smb = smem_u32(sm);
    const int tid  = threadIdx.x;
    const int wid  = tid >> 5;
    const int lane = tid & 31;
    const int seg  = blockIdx.x >> 2;
    const int bn   = (blockIdx.x & 3) * 128;
    const int bm   = blockIdx.y * 128;
    const int wm   = (wid >> 1) * 64;
    const int wn   = (wid & 1) * 64;

    const __half* A = (seg == 0) ? qi : kvi;
    const __half* B = wt + (size_t)seg * 262144;
    const float* bias = (seg == 0) ? bq : (seg == 1) ? bkv : bvg;
    __half* outp = (seg == 0) ? qn : (seg == 1) ? kn : vn;

    float acc[4][8][4];
    #pragma unroll
    for (int i = 0; i < 4; i++)
        #pragma unroll
        for (int j = 0; j < 8; j++)
            #pragma unroll
            for (int r = 0; r < 4; r++) acc[i][j][r] = 0.0f;

    const int lr = lane & 7;
    const int lj = lane >> 3;
    const int lrow = tid >> 3;      // 0..15
    const int lkq  = tid & 7;       // 0..7

    GEMM_MAINLOOP();

    const int g  = lane >> 2;
    const int tg = lane & 3;
    #pragma unroll
    for (int mt = 0; mt < 4; mt++) {
        #pragma unroll
        for (int half = 0; half < 2; half++) {
            const int row = bm + wm + mt * 16 + half * 8 + g;
            float vals[16];
            #pragma unroll
            for (int nt = 0; nt < 8; nt++) {
                const int col = bn + wn + nt * 8 + tg * 2;
                vals[nt * 2 + 0] = acc[mt][nt][half * 2 + 0] + bias[col];
                vals[nt * 2 + 1] = acc[mt][nt][half * 2 + 1] + bias[col + 1];
            }
            if (seg == 2) {
                const float* tv = tvi + (row % LDIM) * CDIM;
                #pragma unroll
                for (int nt = 0; nt < 8; nt++) {
                    const int col = bn + wn + nt * 8 + tg * 2;
                    vals[nt*2+0] = fmaxf(tv[col]   / (1.0f + __expf(-vals[nt*2+0])), 0.0f);
                    vals[nt*2+1] = fmaxf(tv[col+1] / (1.0f + __expf(-vals[nt*2+1])), 0.0f);
                }
            }
            float s = 0.0f;
            #pragma unroll
            for (int i = 0; i < 16; i++) s += vals[i] * vals[i];
            s += __shfl_xor_sync(0xffffffffu, s, 1);
            s += __shfl_xor_sync(0xffffffffu, s, 2);
            const float sc = 1.0f / fmaxf(sqrtf(s), 1e-12f);
            #pragma unroll
            for (int nt = 0; nt < 8; nt++) {
                const int col = bn + wn + nt * 8 + tg * 2;
                *reinterpret_cast<__half2*>(outp + (size_t)row * 512 + col) =
                    __floats2half2_rn(vals[nt*2] * sc, vals[nt*2+1] * sc);
            }
        }
    }
}

// ---------------------------------------------------------------------------
// 5) HMMA attention (R9-exact)
// ---------------------------------------------------------------------------
#define ASTR 72
#define AMAT (32 * ASTR * 2)
#define AWRP (3 * AMAT)

__global__ void __launch_bounds__(128)
attention_hmma(const __half* __restrict__ qn, const __half* __restrict__ kn,
               const __half* __restrict__ vn, __half* __restrict__ xh)
{
    extern __shared__ char sm[];
    const int tid  = threadIdx.x;
    const int w    = tid >> 5;
    const int lane = tid & 31;
    const int unit = blockIdx.x * 4 + w;
    const int bt   = unit >> 3;
    const int h    = unit & 7;
    const size_t base = (size_t)bt * LDIM * CDIM + (size_t)h * DHEAD;

    const uint32_t sqb = smem_u32(sm) + w * AWRP;
    const uint32_t skb = sqb + AMAT;
    const uint32_t svb = skb + AMAT;
    char* sq = sm + w * AWRP;

    #pragma unroll
    for (int i = 0; i < 6; i++) {
        const int idx = lane + i * 32;
        const int r = idx >> 3, c = idx & 7;
        const size_t go = base + (size_t)r * CDIM + c * 8;
        const uint32_t so = (r * ASTR + c * 8) * 2;
        *reinterpret_cast<uint4*>(sq + so)            = *reinterpret_cast<const uint4*>(qn + go);
        *reinterpret_cast<uint4*>(sq + AMAT + so)     = *reinterpret_cast<const uint4*>(kn + go);
        *reinterpret_cast<uint4*>(sq + 2 * AMAT + so) = *reinterpret_cast<const uint4*>(vn + go);
    }
    #pragma unroll
    for (int i = 0; i < 2; i++) {
        const int idx = lane + i * 32;
        const int r = 24 + (idx >> 3), c = idx & 7;
        const uint32_t so = (r * ASTR + c * 8) * 2;
        const uint4 z = make_uint4(0, 0, 0, 0);
        *reinterpret_cast<uint4*>(sq + so)            = z;
        *reinterpret_cast<uint4*>(sq + AMAT + so)     = z;
        *reinterpret_cast<uint4*>(sq + 2 * AMAT + so) = z;
    }
    __syncwarp();

    const int lr = lane & 7;
    const int lj = lane >> 3;
    const int g  = lane >> 2;
    const int tg = lane & 3;

    float s_acc[2][3][4];
    #pragma unroll
    for (int mt = 0; mt < 2; mt++)
        #pragma unroll
        for (int nt = 0; nt < 3; nt++)
            #pragma unroll
            for (int r = 0; r < 4; r++) s_acc[mt][nt][r] = 0.0f;

    #pragma unroll
    for (int ks = 0; ks < 4; ks++) {
        uint32_t qa[2][4], kb[2][4];
        #pragma unroll
        for (int mt = 0; mt < 2; mt++) {
            const int mrow = mt * 16 + (lj & 1) * 8 + lr;
            const int kcol = ks * 16 + (lj >> 1) * 8;
            LDSM4(qa[mt], sqb + (mrow * ASTR + kcol) * 2);
        }
        #pragma unroll
        for (int np = 0; np < 2; np++) {
            const int nrow = np * 16 + (lj >> 1) * 8 + lr;
            const int kcol = ks * 16 + (lj & 1) * 8;
            LDSM4(kb[np], skb + (nrow * ASTR + kcol) * 2);
        }
        #pragma unroll
        for (int mt = 0; mt < 2; mt++)
            #pragma unroll
            for (int nt = 0; nt < 3; nt++)
                MMA16816(s_acc[mt][nt], qa[mt],
                         kb[nt >> 1][(nt & 1) * 2], kb[nt >> 1][(nt & 1) * 2 + 1]);
    }

    #pragma unroll
    for (int mt = 0; mt < 2; mt++) {
        #pragma unroll
        for (int hf = 0; hf < 2; hf++) {
            float m = -1e30f;
            #pragma unroll
            for (int nt = 0; nt < 3; nt++) {
                m = fmaxf(m, s_acc[mt][nt][hf * 2 + 0]);
                m = fmaxf(m, s_acc[mt][nt][hf * 2 + 1]);
            }
            m = fmaxf(m, __shfl_xor_sync(0xffffffffu, m, 1));
            m = fmaxf(m, __shfl_xor_sync(0xffffffffu, m, 2));
            float sum = 0.0f;
            #pragma unroll
            for (int nt = 0; nt < 3; nt++) {
                #pragma unroll
                for (int j = 0; j < 2; j++) {
                    float e = __expf((s_acc[mt][nt][hf * 2 + j] - m) * 0.125f);
                    s_acc[mt][nt][hf * 2 + j] = e;
                    sum += e;
                }
            }
            sum += __shfl_xor_sync(0xffffffffu, sum, 1);
            sum += __shfl_xor_sync(0xffffffffu, sum, 2);
            const float inv = 1.0f / sum;
            #pragma unroll
            for (int nt = 0; nt < 3; nt++) {
                s_acc[mt][nt][hf * 2 + 0] *= inv;
                s_acc[mt][nt][hf * 2 + 1] *= inv;
            }
        }
    }

    uint32_t pah[2][2][4], pal[2][2][4];
    #pragma unroll
    for (int mt = 0; mt < 2; mt++) {
        #pragma unroll
        for (int ks2 = 0; ks2 < 2; ks2++) {
            #pragma unroll
            for (int rr = 0; rr < 4; rr++) {
                const int nt = ks2 * 2 + (rr >> 1);
                if (nt < 3) {
                    const float x = s_acc[mt][nt][(rr & 1) * 2 + 0];
                    const float y = s_acc[mt][nt][(rr & 1) * 2 + 1];
                    const __half hx = __float2half_rn(x), hy = __float2half_rn(y);
                    __half2 hv{hx, hy};
                    __half2 lv{__float2half_rn(x - __half2float(hx)),
                               __float2half_rn(y - __half2float(hy))};
                    pah[mt][ks2][rr] = *reinterpret_cast<uint32_t*>(&hv);
                    pal[mt][ks2][rr] = *reinterpret_cast<uint32_t*>(&lv);
                } else {
                    pah[mt][ks2][rr] = 0;
                    pal[mt][ks2][rr] = 0;
                }
            }
        }
    }

    float o_acc[2][8][4];
    #pragma unroll
    for (int mt = 0; mt < 2; mt++)
        #pragma unroll
        for (int nt = 0; nt < 8; nt++)
            #pragma unroll
            for (int r = 0; r < 4; r++) o_acc[mt][nt][r] = 0.0f;

    #pragma unroll
    for (int ks2 = 0; ks2 < 2; ks2++) {
        uint32_t vb[4][4];
        #pragma unroll
        for (int ng = 0; ng < 4; ng++) {
            const int krow = ks2 * 16 + (lj & 1) * 8 + lr;
            const int ncol = ng * 16 + (lj >> 1) * 8;
            LDSM4T(vb[ng], svb + (krow * ASTR + ncol) * 2);
        }
        #pragma unroll
        for (int mt = 0; mt < 2; mt++)
            #pragma unroll
            for (int nt = 0; nt < 8; nt++) {
                const uint32_t b0 = vb[nt >> 1][(nt & 1) * 2];
                const uint32_t b1 = vb[nt >> 1][(nt & 1) * 2 + 1];
                MMA16816(o_acc[mt][nt], pah[mt][ks2], b0, b1);
                MMA16816(o_acc[mt][nt], pal[mt][ks2], b0, b1);
            }
    }

    #pragma unroll
    for (int mt = 0; mt < 2; mt++) {
        const int r0 = mt * 16 + g;
        #pragma unroll
        for (int nt = 0; nt < 8; nt++) {
            const int col = nt * 8 + tg * 2;
            *reinterpret_cast<__half2*>(xh + base + (size_t)r0 * CDIM + col) =
                __floats2half2_rn(o_acc[mt][nt][0], o_acc[mt][nt][1]);
        }
        if (mt == 0) {
            const int r1 = 8 + g;
            #pragma unroll
            for (int nt = 0; nt < 8; nt++) {
                const int col = nt * 8 + tg * 2;
                *reinterpret_cast<__half2*>(xh + base + (size_t)r1 * CDIM + col) =
                    __floats2half2_rn(o_acc[0][nt][2], o_acc[0][nt][3]);
            }
        }
    }
}

// ---------------------------------------------------------------------------
// 6) final GEMM: grid (4, 384), block 128
// ---------------------------------------------------------------------------
__global__ void __launch_bounds__(128, 2)
final_mma(const __half* __restrict__ A, const __half* __restrict__ B,
          const float* __restrict__ bias, const float* __restrict__ shortcut,
          float* __restrict__ outf)
{
    extern __shared__ char sm[];
    const uint32_t smb = smem_u32(sm);
    const int tid  = threadIdx.x;
    const int wid  = tid >> 5;
    const int lane = tid & 31;
    const int bn   = blockIdx.x * 128;
    const int bm   = blockIdx.y * 128;
    const int wm   = (wid >> 1) * 64;
    const int wn   = (wid & 1) * 64;

    float acc[4][8][4];
    #pragma unroll
    for (int i = 0; i < 4; i++)
        #pragma unroll
        for (int j = 0; j < 8; j++)
            #pragma unroll
            for (int r = 0; r < 4; r++) acc[i][j][r] = 0.0f;

    const int lr = lane & 7;
    const int lj = lane >> 3;
    const int lrow = tid >> 3;
    const int lkq  = tid & 7;

    GEMM_MAINLOOP();

    const int g  = lane >> 2;
    const int tg = lane & 3;
    #pragma unroll
    for (int mt = 0; mt < 4; mt++) {
        #pragma unroll
        for (int half = 0; half < 2; half++) {
            const int row = bm + wm + mt * 16 + half * 8 + g;
            #pragma unroll
            for (int nt = 0; nt < 8; nt++) {
                const int col = bn + wn + nt * 8 + tg * 2;
                const float2 e2 = *reinterpret_cast<const float2*>(
                    shortcut + (size_t)row * 512 + col);
                *reinterpret_cast<float2*>(outf + (size_t)row * 512 + col) =
                    make_float2(acc[mt][nt][half * 2 + 0] + bias[col]     + e2.x,
                                acc[mt][nt][half * 2 + 1] + bias[col + 1] + e2.y);
            }
        }
    }
}

// ---------------------------------------------------------------------------
// Launch
// ---------------------------------------------------------------------------
extern "C" void kernel_launch(void* const* d_in, const int* in_sizes, int n_in,
                              void* d_out, int out_size)
{
    const float* q      = (const float*)d_in[0];
    const float* kv     = (const float*)d_in[1];
    const float* Wq     = (const float*)d_in[2];
    const float* bq     = (const float*)d_in[3];
    const float* Wkv    = (const float*)d_in[4];
    const float* bkv    = (const float*)d_in[5];
    const float* Wg     = (const float*)d_in[6];
    const float* bg     = (const float*)d_in[7];
    const float* v_init = (const float*)d_in[8];
    const float* Wm     = (const float*)d_in[9];
    const float* bm     = (const float*)d_in[10];
    float* out = (float*)d_out;

    float *p_tvi, *p_bvg, *p_wvgp;
    __half *p_qi, *p_kvi, *p_qn, *p_kn, *p_vn, *p_xh, *p_wt;
    cudaGetSymbolAddress((void**)&p_tvi,  g_tvi);
    cudaGetSymbolAddress((void**)&p_bvg,  g_bvg);
    cudaGetSymbolAddress((void**)&p_wvgp, g_wvgp);
    cudaGetSymbolAddress((void**)&p_qi,   g_qi);
    cudaGetSymbolAddress((void**)&p_kvi,  g_kvi);
    cudaGetSymbolAddress((void**)&p_qn,   g_qn);
    cudaGetSymbolAddress((void**)&p_kn,   g_kn);
    cudaGetSymbolAddress((void**)&p_vn,   g_vn);
    cudaGetSymbolAddress((void**)&p_xh,   g_xh);
    cudaGetSymbolAddress((void**)&p_wt,   g_wt);

    const int SMEM = 2 * BUF;             // 73728
    const int ASMEM = 4 * AWRP;           // 55296
    cudaFuncSetAttribute(proj_mma,       cudaFuncAttributeMaxDynamicSharedMemorySize, SMEM);
    cudaFuncSetAttribute(final_mma,      cudaFuncAttributeMaxDynamicSharedMemorySize, SMEM);
    cudaFuncSetAttribute(attention_hmma, cudaFuncAttributeMaxDynamicSharedMemorySize, ASMEM);

    conv_both<<<2 * N4 / 256, 256>>>(q, kv, p_qi, p_kvi);
    prepare<<<946, 256>>>(Wq, Wkv, Wg, Wm, bkv, bg, v_init, p_wt, p_wvgp, p_tvi, p_bvg);
    finish_wvg<<<256, 256>>>(p_wvgp, p_wt);
    proj_mma<<<dim3(12, MROWS / 128), 128, SMEM>>>(
        p_qi, p_kvi, p_wt, bq, bkv, p_bvg, p_tvi, p_qn, p_kn, p_vn);
    attention_hmma<<<MROWS / LDIM * HEADS / 4, 128, ASMEM>>>(p_qn, p_kn, p_vn, p_xh);
    final_mma<<<dim3(4, MROWS / 128), 128, SMEM>>>(p_xh, p_wt + 786432, bm, q, out);
}

// round 15
// speedup vs baseline: 1.1073x; 1.1073x over previous
#include <cuda_runtime.h>
#include <cuda_fp16.h>
#include <math.h>
#include <cstdint>

#define MROWS 49152
#define CDIM  512
#define LDIM  24
#define HEADS 8
#define DHEAD 64

// ---------------------------------------------------------------------------
// Device scratch
// ---------------------------------------------------------------------------
__device__ float  g_tvi[LDIM * CDIM];
__device__ float  g_bvg[CDIM];
__device__ float  g_wvgp[8 * 512 * 512];
__device__ __half g_qi [MROWS * CDIM];
__device__ __half g_kvi[MROWS * CDIM];
__device__ __half g_qn [MROWS * CDIM];
__device__ __half g_kn [MROWS * CDIM];
__device__ __half g_vn [MROWS * CDIM];
__device__ __half g_xh [MROWS * CDIM];
// Transposed fp16 weights [N][K]: q:0, k:262144, vg:524288, m:786432
__device__ __half g_wt [1048576];

// ---------------------------------------------------------------------------
// PTX helpers
// ---------------------------------------------------------------------------
__device__ __forceinline__ uint32_t smem_u32(const void* p) {
    uint32_t a;
    asm("{ .reg .u64 t; cvta.to.shared.u64 t, %1; cvt.u32.u64 %0, t; }" : "=r"(a) : "l"(p));
    return a;
}
__device__ __forceinline__ void cp16(uint32_t s, const void* g) {
    asm volatile("cp.async.cg.shared.global [%0], [%1], 16;" :: "r"(s), "l"(g));
}
#define CP_COMMIT() asm volatile("cp.async.commit_group;")
#define CP_WAIT(n)  asm volatile("cp.async.wait_group %0;" :: "n"(n))

#define LDSM4(r, a)                                                        \
    asm volatile("ldmatrix.sync.aligned.m8n8.x4.shared.b16 {%0,%1,%2,%3}, [%4];" \
        : "=r"((r)[0]), "=r"((r)[1]), "=r"((r)[2]), "=r"((r)[3]) : "r"(a))

#define LDSM4T(r, a)                                                       \
    asm volatile("ldmatrix.sync.aligned.m8n8.x4.trans.shared.b16 {%0,%1,%2,%3}, [%4];" \
        : "=r"((r)[0]), "=r"((r)[1]), "=r"((r)[2]), "=r"((r)[3]) : "r"(a))

#define MMA16816(c, a, b0, b1)                                             \
    asm volatile(                                                          \
        "mma.sync.aligned.m16n8k16.row.col.f32.f16.f16.f32 "               \
        "{%0,%1,%2,%3},{%4,%5,%6,%7},{%8,%9},{%0,%1,%2,%3};"               \
        : "+f"((c)[0]), "+f"((c)[1]), "+f"((c)[2]), "+f"((c)[3])           \
        : "r"((a)[0]), "r"((a)[1]), "r"((a)[2]), "r"((a)[3]),              \
          "r"(b0), "r"(b1))

// ---------------------------------------------------------------------------
// 1) conv_both (R9-exact)
// ---------------------------------------------------------------------------
#define N4 (MROWS * CDIM / 4)
__global__ void conv_both(const float* __restrict__ q, const float* __restrict__ kv,
                          __half* __restrict__ qi, __half* __restrict__ kvi) {
    int i = blockIdx.x * 256 + threadIdx.x;
    const float* src = (i < N4) ? q : kv;
    __half* dst = (i < N4) ? qi : kvi;
    int j = (i < N4) ? i : i - N4;
    float4 v = reinterpret_cast<const float4*>(src)[j];
    reinterpret_cast<__half2*>(dst)[j * 2 + 0] = __floats2half2_rn(v.x, v.y);
    reinterpret_cast<__half2*>(dst)[j * 2 + 1] = __floats2half2_rn(v.z, v.w);
}

// ---------------------------------------------------------------------------
// 2) prepare (R9-exact)
// ---------------------------------------------------------------------------
__global__ void __launch_bounds__(256)
prepare(const float* __restrict__ Wq, const float* __restrict__ Wkv,
        const float* __restrict__ Wg, const float* __restrict__ Wm,
        const float* __restrict__ bkv, const float* __restrict__ bg,
        const float* __restrict__ v_init,
        __half* __restrict__ wt, float* __restrict__ wvgp,
        float* __restrict__ tvi, float* __restrict__ bvg)
{
    __shared__ float t[32][33];
    __shared__ float As[16][128];
    __shared__ float Bs[16][128];

    const int bx = blockIdx.x;
    const int tx = threadIdx.x & 31;
    const int ty = threadIdx.x >> 5;
    const int flat = threadIdx.x;

    if (bx < 768) {
        const int seg = bx >> 8;
        const int local = bx & 255;
        const int n0 = (local & 15) * 32, k0 = (local >> 4) * 32;
        const float* W = (seg == 0) ? Wq : (seg == 1) ? Wkv : Wm;
        const int N = (seg == 1) ? 1024 : 512;
        __half* dst = wt + ((seg == 0) ? 0 : (seg == 1) ? 262144 : 786432);
        #pragma unroll
        for (int i = 0; i < 32; i += 8)
            t[ty + i][tx] = W[(size_t)(k0 + ty + i) * N + n0 + tx];
        __syncthreads();
        #pragma unroll
        for (int i = 0; i < 32; i += 8)
            dst[(size_t)(n0 + ty + i) * 512 + k0 + tx] = __float2half(t[tx][ty + i]);
    } else if (bx < 896) {
        const int local = bx - 768;
        const int tile = local >> 3, slice = local & 7;
        const int m0 = (tile >> 2) * 128, n0 = (tile & 3) * 128;
        const int j0 = slice * 64;
        const int px = flat & 15, py = flat >> 4;
        float acc[8][8];
        #pragma unroll
        for (int i = 0; i < 8; i++)
            #pragma unroll
            for (int j = 0; j < 8; j++) acc[i][j] = 0.0f;
        for (int jc = 0; jc < 64; jc += 16) {
            #pragma unroll
            for (int i = 0; i < 2; i++) {
                int lin = flat + i * 256;
                int ar = lin >> 2, ac = (lin & 3) * 4;
                float4 av = *reinterpret_cast<const float4*>(
                    Wkv + (size_t)(m0 + ar) * 1024 + 512 + j0 + jc + ac);
                As[ac + 0][ar] = av.x; As[ac + 1][ar] = av.y;
                As[ac + 2][ar] = av.z; As[ac + 3][ar] = av.w;
                int br = lin >> 5, bc = (lin & 31) * 4;
                *reinterpret_cast<float4*>(&Bs[br][bc]) =
                    *reinterpret_cast<const float4*>(Wg + (size_t)(j0 + jc + br) * 512 + n0 + bc);
            }
            __syncthreads();
            #pragma unroll
            for (int kk = 0; kk < 16; kk++) {
                float a[8], b[8];
                #pragma unroll
                for (int i = 0; i < 8; i++) { a[i] = As[kk][py * 8 + i]; b[i] = Bs[kk][px * 8 + i]; }
                #pragma unroll
                for (int i = 0; i < 8; i++)
                    #pragma unroll
                    for (int j = 0; j < 8; j++) acc[i][j] += a[i] * b[j];
            }
            __syncthreads();
        }
        #pragma unroll
        for (int i = 0; i < 8; i++)
            #pragma unroll
            for (int j = 0; j < 8; j++)
                wvgp[(size_t)slice * 262144 + (size_t)(m0 + py * 8 + i) * 512 + n0 + px * 8 + j] = acc[i][j];
    } else if (bx < 944) {
        int i = (bx - 896) * 256 + flat;
        tvi[i] = tanhf(v_init[i]);
    } else {
        int n = (bx - 944) * 256 + flat;
        if (n < 512) {
            float s = bg[n];
            for (int j = 0; j < 512; j++) s += bkv[512 + j] * Wg[(size_t)j * 512 + n];
            bvg[n] = s;
        }
    }
}

// ---------------------------------------------------------------------------
// 3) finish_wvg (R9-exact)
// ---------------------------------------------------------------------------
__global__ void __launch_bounds__(256)
finish_wvg(const float* __restrict__ wvgp, __half* __restrict__ wt) {
    __shared__ float t[32][33];
    const int nb = blockIdx.x & 15, mb = blockIdx.x >> 4;
    const int n0 = nb * 32, m0 = mb * 32;
    const int tx = threadIdx.x & 31, ty = threadIdx.x >> 5;
    #pragma unroll
    for (int i = 0; i < 32; i += 8) {
        float s = 0.0f;
        #pragma unroll
        for (int sl = 0; sl < 8; sl++)
            s += wvgp[(size_t)sl * 262144 + (size_t)(m0 + ty + i) * 512 + n0 + tx];
        t[ty + i][tx] = s;
    }
    __syncthreads();
    #pragma unroll
    for (int i = 0; i < 32; i += 8)
        wt[524288 + (size_t)(n0 + ty + i) * 512 + m0 + tx] = __float2half(t[tx][ty + i]);
}

// ---------------------------------------------------------------------------
// GEMM mainloop — R9-exact: CTA 128x128, warp 32x64, BK=64, 2-stage,
// one barrier per chunk: wait -> sync -> load next -> compute.
// ---------------------------------------------------------------------------
#define SROW 144
#define MAT  18432
#define BUF  36864

#define LOAD_CHUNK(c, buf) do {                                              \
    const int kc0 = (c) * 64;                                                \
    const uint32_t sb = smb + (buf) * BUF;                                   \
    _Pragma("unroll")                                                        \
    for (int it = 0; it < 4; it++) {                                         \
        const int row = lrow + it * 32;                                      \
        const uint32_t so = row * SROW + lkq * 16;                           \
        cp16(sb + so,       A + (size_t)(bm + row) * 512 + kc0 + lkq * 8);   \
        cp16(sb + MAT + so, B + (size_t)(bn + row) * 512 + kc0 + lkq * 8);   \
    }                                                                        \
    CP_COMMIT();                                                             \
} while (0)

#define GEMM_MAINLOOP()                                                      \
    LOAD_CHUNK(0, 0);                                                        \
    for (int c = 0; c < 8; c++) {                                            \
        const int buf = c & 1;                                               \
        CP_WAIT(0);                                                          \
        __syncthreads();                                                     \
        if (c < 7) LOAD_CHUNK(c + 1, buf ^ 1);                               \
        const uint32_t sb = smb + buf * BUF;                                 \
        _Pragma("unroll")                                                    \
        for (int ks = 0; ks < 4; ks++) {                                     \
            uint32_t afr[2][4], bfr[4][4];                                   \
            _Pragma("unroll")                                                \
            for (int mt = 0; mt < 2; mt++) {                                 \
                const int mrow = wm + mt * 16 + (lj & 1) * 8 + lr;           \
                const int kcol = ks * 16 + (lj >> 1) * 8;                    \
                LDSM4(afr[mt], sb + mrow * SROW + kcol * 2);                 \
            }                                                                \
            _Pragma("unroll")                                                \
            for (int np = 0; np < 4; np++) {                                 \
                const int nrow = wn + np * 16 + (lj >> 1) * 8 + lr;          \
                const int kcol = ks * 16 + (lj & 1) * 8;                     \
                LDSM4(bfr[np], sb + MAT + nrow * SROW + kcol * 2);           \
            }                                                                \
            _Pragma("unroll")                                                \
            for (int mt = 0; mt < 2; mt++)                                   \
                _Pragma("unroll")                                            \
                for (int nt = 0; nt < 8; nt++)                               \
                    MMA16816(acc[mt][nt], afr[mt],                           \
                             bfr[nt >> 1][(nt & 1) * 2],                     \
                             bfr[nt >> 1][(nt & 1) * 2 + 1]);                \
        }                                                                    \
    }

// ---------------------------------------------------------------------------
// 4) proj_mma (R9-exact + __expf)
// ---------------------------------------------------------------------------
__global__ void __launch_bounds__(256, 2)
proj_mma(const __half* __restrict__ qi, const __half* __restrict__ kvi,
         const __half* __restrict__ wt,
         const float* __restrict__ bq, const float* __restrict__ bkv,
         const float* __restrict__ bvg, const float* __restrict__ tvi,
         __half* __restrict__ qn, __half* __restrict__ kn, __half* __restrict__ vn)
{
    extern __shared__ char sm[];
    const uint32_t smb = smem_u32(sm);
    const int tid  = threadIdx.x;
    const int wid  = tid >> 5;
    const int lane = tid & 31;
    const int seg  = blockIdx.x >> 2;
    const int bn   = (blockIdx.x & 3) * 128;
    const int bm   = blockIdx.y * 128;
    const int wm   = (wid >> 1) * 32;
    const int wn   = (wid & 1) * 64;

    const __half* A = (seg == 0) ? qi : kvi;
    const __half* B = wt + (size_t)seg * 262144;
    const float* bias = (seg == 0) ? bq : (seg == 1) ? bkv : bvg;
    __half* outp = (seg == 0) ? qn : (seg == 1) ? kn : vn;

    float acc[2][8][4];
    #pragma unroll
    for (int i = 0; i < 2; i++)
        #pragma unroll
        for (int j = 0; j < 8; j++)
            #pragma unroll
            for (int r = 0; r < 4; r++) acc[i][j][r] = 0.0f;

    const int lr = lane & 7;
    const int lj = lane >> 3;
    const int lrow = tid >> 3;
    const int lkq  = tid & 7;

    GEMM_MAINLOOP();

    const int g  = lane >> 2;
    const int tg = lane & 3;
    #pragma unroll
    for (int mt = 0; mt < 2; mt++) {
        #pragma unroll
        for (int half = 0; half < 2; half++) {
            const int row = bm + wm + mt * 16 + half * 8 + g;
            float vals[16];
            #pragma unroll
            for (int nt = 0; nt < 8; nt++) {
                const int col = bn + wn + nt * 8 + tg * 2;
                vals[nt * 2 + 0] = acc[mt][nt][half * 2 + 0] + bias[col];
                vals[nt * 2 + 1] = acc[mt][nt][half * 2 + 1] + bias[col + 1];
            }
            if (seg == 2) {
                const float* tv = tvi + (row % LDIM) * CDIM;
                #pragma unroll
                for (int nt = 0; nt < 8; nt++) {
                    const int col = bn + wn + nt * 8 + tg * 2;
                    vals[nt*2+0] = fmaxf(tv[col]   / (1.0f + __expf(-vals[nt*2+0])), 0.0f);
                    vals[nt*2+1] = fmaxf(tv[col+1] / (1.0f + __expf(-vals[nt*2+1])), 0.0f);
                }
            }
            float s = 0.0f;
            #pragma unroll
            for (int i = 0; i < 16; i++) s += vals[i] * vals[i];
            s += __shfl_xor_sync(0xffffffffu, s, 1);
            s += __shfl_xor_sync(0xffffffffu, s, 2);
            const float sc = 1.0f / fmaxf(sqrtf(s), 1e-12f);
            #pragma unroll
            for (int nt = 0; nt < 8; nt++) {
                const int col = bn + wn + nt * 8 + tg * 2;
                *reinterpret_cast<__half2*>(outp + (size_t)row * 512 + col) =
                    __floats2half2_rn(vals[nt*2] * sc, vals[nt*2+1] * sc);
            }
        }
    }
}

// ---------------------------------------------------------------------------
// 5) HMMA attention: Q/K stored 24 rows (over-read lands in next field,
//    garbage confined to unused regs / never-stored rows), V 32 rows
//    zero-padded. Single-pass fp16 P (no hi/lo split): 32 PV MMAs.
//    smem 46080/block + regs<=102 -> 5 blocks/SM.
// ---------------------------------------------------------------------------
#define ASTR 72
#define QKB  (24 * ASTR * 2)     // 3456 bytes per 24-row matrix
#define VB   (32 * ASTR * 2)     // 4608 bytes (V padded)
#define AWRP (2 * QKB + VB)      // 11520 bytes per warp

__global__ void __launch_bounds__(128, 5)
attention_hmma(const __half* __restrict__ qn, const __half* __restrict__ kn,
               const __half* __restrict__ vn, __half* __restrict__ xh)
{
    extern __shared__ char sm[];
    const int tid  = threadIdx.x;
    const int w    = tid >> 5;
    const int lane = tid & 31;
    const int unit = blockIdx.x * 4 + w;
    const int bt   = unit >> 3;
    const int h    = unit & 7;
    const size_t base = (size_t)bt * LDIM * CDIM + (size_t)h * DHEAD;

    const uint32_t sqb = smem_u32(sm) + w * AWRP;
    const uint32_t skb = sqb + QKB;
    const uint32_t svb = skb + QKB;
    char* sq = sm + w * AWRP;

    // data rows 0..23 of q,k,v
    #pragma unroll
    for (int i = 0; i < 6; i++) {
        const int idx = lane + i * 32;
        const int r = idx >> 3, c = idx & 7;
        const size_t go = base + (size_t)r * CDIM + c * 8;
        const uint32_t so = (r * ASTR + c * 8) * 2;
        *reinterpret_cast<uint4*>(sq + so)           = *reinterpret_cast<const uint4*>(qn + go);
        *reinterpret_cast<uint4*>(sq + QKB + so)     = *reinterpret_cast<const uint4*>(kn + go);
        *reinterpret_cast<uint4*>(sq + 2 * QKB + so) = *reinterpret_cast<const uint4*>(vn + go);
    }
    // zero-pad V rows 24..31 only
    #pragma unroll
    for (int i = 0; i < 2; i++) {
        const int idx = lane + i * 32;
        const int r = 24 + (idx >> 3), c = idx & 7;
        *reinterpret_cast<uint4*>(sq + 2 * QKB + (r * ASTR + c * 8) * 2) =
            make_uint4(0, 0, 0, 0);
    }
    __syncwarp();

    const int lr = lane & 7;
    const int lj = lane >> 3;
    const int g  = lane >> 2;
    const int tg = lane & 3;

    // ---- S = Q K^T
    float s_acc[2][3][4];
    #pragma unroll
    for (int mt = 0; mt < 2; mt++)
        #pragma unroll
        for (int nt = 0; nt < 3; nt++)
            #pragma unroll
            for (int r = 0; r < 4; r++) s_acc[mt][nt][r] = 0.0f;

    #pragma unroll
    for (int ks = 0; ks < 4; ks++) {
        uint32_t qa[2][4], kb[2][4];
        #pragma unroll
        for (int mt = 0; mt < 2; mt++) {
            const int mrow = mt * 16 + (lj & 1) * 8 + lr;
            const int kcol = ks * 16 + (lj >> 1) * 8;
            LDSM4(qa[mt], sqb + (mrow * ASTR + kcol) * 2);
        }
        #pragma unroll
        for (int np = 0; np < 2; np++) {
            const int nrow = np * 16 + (lj >> 1) * 8 + lr;
            const int kcol = ks * 16 + (lj & 1) * 8;
            LDSM4(kb[np], skb + (nrow * ASTR + kcol) * 2);
        }
        #pragma unroll
        for (int mt = 0; mt < 2; mt++)
            #pragma unroll
            for (int nt = 0; nt < 3; nt++)
                MMA16816(s_acc[mt][nt], qa[mt],
                         kb[nt >> 1][(nt & 1) * 2], kb[nt >> 1][(nt & 1) * 2 + 1]);
    }

    // ---- softmax (rows 24-31 garbage stays confined to unused regs)
    #pragma unroll
    for (int mt = 0; mt < 2; mt++) {
        #pragma unroll
        for (int hf = 0; hf < 2; hf++) {
            float m = -1e30f;
            #pragma unroll
            for (int nt = 0; nt < 3; nt++) {
                m = fmaxf(m, s_acc[mt][nt][hf * 2 + 0]);
                m = fmaxf(m, s_acc[mt][nt][hf * 2 + 1]);
            }
            m = fmaxf(m, __shfl_xor_sync(0xffffffffu, m, 1));
            m = fmaxf(m, __shfl_xor_sync(0xffffffffu, m, 2));
            float sum = 0.0f;
            #pragma unroll
            for (int nt = 0; nt < 3; nt++) {
                #pragma unroll
                for (int j = 0; j < 2; j++) {
                    float e = __expf((s_acc[mt][nt][hf * 2 + j] - m) * 0.125f);
                    s_acc[mt][nt][hf * 2 + j] = e;
                    sum += e;
                }
            }
            sum += __shfl_xor_sync(0xffffffffu, sum, 1);
            sum += __shfl_xor_sync(0xffffffffu, sum, 2);
            const float inv = 1.0f / sum;
            #pragma unroll
            for (int nt = 0; nt < 3; nt++) {
                s_acc[mt][nt][hf * 2 + 0] *= inv;
                s_acc[mt][nt][hf * 2 + 1] *= inv;
            }
        }
    }

    // ---- P -> fp16 A fragments, single pass (P in [0,1], eps ~5e-4 ok)
    uint32_t pa[2][2][4];
    #pragma unroll
    for (int mt = 0; mt < 2; mt++) {
        #pragma unroll
        for (int ks2 = 0; ks2 < 2; ks2++) {
            #pragma unroll
            for (int rr = 0; rr < 4; rr++) {
                const int nt = ks2 * 2 + (rr >> 1);
                if (nt < 3) {
                    __half2 hv = __floats2half2_rn(s_acc[mt][nt][(rr & 1) * 2 + 0],
                                                   s_acc[mt][nt][(rr & 1) * 2 + 1]);
                    pa[mt][ks2][rr] = *reinterpret_cast<uint32_t*>(&hv);
                } else {
                    pa[mt][ks2][rr] = 0;
                }
            }
        }
    }

    // ---- O = P V
    float o_acc[2][8][4];
    #pragma unroll
    for (int mt = 0; mt < 2; mt++)
        #pragma unroll
        for (int nt = 0; nt < 8; nt++)
            #pragma unroll
            for (int r = 0; r < 4; r++) o_acc[mt][nt][r] = 0.0f;

    #pragma unroll
    for (int ks2 = 0; ks2 < 2; ks2++) {
        uint32_t vb[4][4];
        #pragma unroll
        for (int ng = 0; ng < 4; ng++) {
            const int krow = ks2 * 16 + (lj & 1) * 8 + lr;
            const int ncol = ng * 16 + (lj >> 1) * 8;
            LDSM4T(vb[ng], svb + (krow * ASTR + ncol) * 2);
        }
        #pragma unroll
        for (int mt = 0; mt < 2; mt++)
            #pragma unroll
            for (int nt = 0; nt < 8; nt++)
                MMA16816(o_acc[mt][nt], pa[mt][ks2],
                         vb[nt >> 1][(nt & 1) * 2], vb[nt >> 1][(nt & 1) * 2 + 1]);
    }

    // ---- store rows < 24
    #pragma unroll
    for (int mt = 0; mt < 2; mt++) {
        const int r0 = mt * 16 + g;
        #pragma unroll
        for (int nt = 0; nt < 8; nt++) {
            const int col = nt * 8 + tg * 2;
            *reinterpret_cast<__half2*>(xh + base + (size_t)r0 * CDIM + col) =
                __floats2half2_rn(o_acc[mt][nt][0], o_acc[mt][nt][1]);
        }
        if (mt == 0) {
            const int r1 = 8 + g;
            #pragma unroll
            for (int nt = 0; nt < 8; nt++) {
                const int col = nt * 8 + tg * 2;
                *reinterpret_cast<__half2*>(xh + base + (size_t)r1 * CDIM + col) =
                    __floats2half2_rn(o_acc[0][nt][2], o_acc[0][nt][3]);
            }
        }
    }
}

// ---------------------------------------------------------------------------
// 6) final GEMM (R9-exact)
// ---------------------------------------------------------------------------
__global__ void __launch_bounds__(256, 2)
final_mma(const __half* __restrict__ A, const __half* __restrict__ B,
          const float* __restrict__ bias, const float* __restrict__ shortcut,
          float* __restrict__ outf)
{
    extern __shared__ char sm[];
    const uint32_t smb = smem_u32(sm);
    const int tid  = threadIdx.x;
    const int wid  = tid >> 5;
    const int lane = tid & 31;
    const int bn   = blockIdx.x * 128;
    const int bm   = blockIdx.y * 128;
    const int wm   = (wid >> 1) * 32;
    const int wn   = (wid & 1) * 64;

    float acc[2][8][4];
    #pragma unroll
    for (int i = 0; i < 2; i++)
        #pragma unroll
        for (int j = 0; j < 8; j++)
            #pragma unroll
            for (int r = 0; r < 4; r++) acc[i][j][r] = 0.0f;

    const int lr = lane & 7;
    const int lj = lane >> 3;
    const int lrow = tid >> 3;
    const int lkq  = tid & 7;

    GEMM_MAINLOOP();

    const int g  = lane >> 2;
    const int tg = lane & 3;
    #pragma unroll
    for (int mt = 0; mt < 2; mt++) {
        #pragma unroll
        for (int half = 0; half < 2; half++) {
            const int row = bm + wm + mt * 16 + half * 8 + g;
            #pragma unroll
            for (int nt = 0; nt < 8; nt++) {
                const int col = bn + wn + nt * 8 + tg * 2;
                const float2 e2 = *reinterpret_cast<const float2*>(
                    shortcut + (size_t)row * 512 + col);
                *reinterpret_cast<float2*>(outf + (size_t)row * 512 + col) =
                    make_float2(acc[mt][nt][half * 2 + 0] + bias[col]     + e2.x,
                                acc[mt][nt][half * 2 + 1] + bias[col + 1] + e2.y);
            }
        }
    }
}

// ---------------------------------------------------------------------------
// Launch
// ---------------------------------------------------------------------------
extern "C" void kernel_launch(void* const* d_in, const int* in_sizes, int n_in,
                              void* d_out, int out_size)
{
    const float* q      = (const float*)d_in[0];
    const float* kv     = (const float*)d_in[1];
    const float* Wq     = (const float*)d_in[2];
    const float* bq     = (const float*)d_in[3];
    const float* Wkv    = (const float*)d_in[4];
    const float* bkv    = (const float*)d_in[5];
    const float* Wg     = (const float*)d_in[6];
    const float* bg     = (const float*)d_in[7];
    const float* v_init = (const float*)d_in[8];
    const float* Wm     = (const float*)d_in[9];
    const float* bm     = (const float*)d_in[10];
    float* out = (float*)d_out;

    float *p_tvi, *p_bvg, *p_wvgp;
    __half *p_qi, *p_kvi, *p_qn, *p_kn, *p_vn, *p_xh, *p_wt;
    cudaGetSymbolAddress((void**)&p_tvi,  g_tvi);
    cudaGetSymbolAddress((void**)&p_bvg,  g_bvg);
    cudaGetSymbolAddress((void**)&p_wvgp, g_wvgp);
    cudaGetSymbolAddress((void**)&p_qi,   g_qi);
    cudaGetSymbolAddress((void**)&p_kvi,  g_kvi);
    cudaGetSymbolAddress((void**)&p_qn,   g_qn);
    cudaGetSymbolAddress((void**)&p_kn,   g_kn);
    cudaGetSymbolAddress((void**)&p_vn,   g_vn);
    cudaGetSymbolAddress((void**)&p_xh,   g_xh);
    cudaGetSymbolAddress((void**)&p_wt,   g_wt);

    const int SMEM = 2 * BUF;             // 73728
    const int ASMEM = 4 * AWRP;           // 46080
    cudaFuncSetAttribute(proj_mma,       cudaFuncAttributeMaxDynamicSharedMemorySize, SMEM);
    cudaFuncSetAttribute(final_mma,      cudaFuncAttributeMaxDynamicSharedMemorySize, SMEM);
    cudaFuncSetAttribute(attention_hmma, cudaFuncAttributeMaxDynamicSharedMemorySize, ASMEM);

    conv_both<<<2 * N4 / 256, 256>>>(q, kv, p_qi, p_kvi);
    prepare<<<946, 256>>>(Wq, Wkv, Wg, Wm, bkv, bg, v_init, p_wt, p_wvgp, p_tvi, p_bvg);
    finish_wvg<<<256, 256>>>(p_wvgp, p_wt);
    proj_mma<<<dim3(12, MROWS / 128), 256, SMEM>>>(
        p_qi, p_kvi, p_wt, bq, bkv, p_bvg, p_tvi, p_qn, p_kn, p_vn);
    attention_hmma<<<MROWS / LDIM * HEADS / 4, 128, ASMEM>>>(p_qn, p_kn, p_vn, p_xh);
    final_mma<<<dim3(4, MROWS / 128), 256, SMEM>>>(p_xh, p_wt + 786432, bm, q, out);
}